// round 2
// baseline (speedup 1.0000x reference)
#include <cuda_runtime.h>

#define B 8
#define L 2048
#define H 8
#define D 64
#define S 40
#define U 40
#define NBH (B*H)
#define SPLIT 8
#define CHUNK (L/SPLIT)   // 256
#define NEG_INF (-3.4e38f)

// ---------------- scratch (device globals; no allocation) ----------------
__device__ float g_M[NBH*L];             // sparsity metric per (bh, l)
__device__ int   g_Mtop[NBH*U];          // top-U query indices per bh
__device__ float g_Vpart[NBH*SPLIT*D];   // partial V sums
__device__ float g_pO[NBH*SPLIT*U*D];    // split attention partial outputs
__device__ float g_pm[NBH*SPLIT*U];      // split local max
__device__ float g_pl[NBH*SPLIT*U];      // split local sum-exp

// ---------------- K1: M[bh,l] = max_s(q.k_s) - mean_s(q.k_s) ----------------
__global__ void __launch_bounds__(256) k1_sampleM(const float* __restrict__ Qg,
                                                  const float* __restrict__ Kg,
                                                  const int*   __restrict__ idxs) {
    int warp = threadIdx.x >> 5;
    int lane = threadIdx.x & 31;
    int grp  = lane >> 3;        // 4 queries per warp
    int sub  = lane & 7;         // 8 lanes per query
    int g    = blockIdx.x * 32 + warp * 4 + grp;   // g = bh*L + l
    int l    = g & (L - 1);
    int bh   = g >> 11;
    int b    = bh >> 3, h = bh & 7;

    const float4* qrow = (const float4*)(Qg + ((b*L + l)*H + h)*D);
    float4 q0 = qrow[sub];
    float4 q1 = qrow[sub + 8];
    const int* myidx = idxs + l * S;

    float maxv = NEG_INF, sumv = 0.f;
    #pragma unroll 4
    for (int s = 0; s < S; s++) {
        int kidx = myidx[s];
        const float4* krow = (const float4*)(Kg + ((b*L + kidx)*H + h)*D);
        float4 k0 = krow[sub];
        float4 k1 = krow[sub + 8];
        float p = q0.x*k0.x + q0.y*k0.y + q0.z*k0.z + q0.w*k0.w
                + q1.x*k1.x + q1.y*k1.y + q1.z*k1.z + q1.w*k1.w;
        p += __shfl_xor_sync(0xffffffffu, p, 1);
        p += __shfl_xor_sync(0xffffffffu, p, 2);
        p += __shfl_xor_sync(0xffffffffu, p, 4);
        maxv = fmaxf(maxv, p);
        sumv += p;
    }
    if (sub == 0) g_M[bh*L + l] = maxv - sumv * (1.0f / S);
}

// ---------------- K2: top-U per bh via iterative argmax ----------------
__global__ void __launch_bounds__(256) k2_topk() {
    __shared__ float sv[L];
    __shared__ float rv[8];
    __shared__ int   ri[8];
    int bh = blockIdx.x, tid = threadIdx.x;
    for (int i = tid; i < L; i += 256) sv[i] = g_M[bh*L + i];
    __syncthreads();
    for (int it = 0; it < U; it++) {
        float v = NEG_INF; int id = 0;
        for (int i = tid; i < L; i += 256) {
            float x = sv[i];
            if (x > v) { v = x; id = i; }      // ascending i -> keeps smallest idx on ties
        }
        for (int o = 16; o; o >>= 1) {
            float ov = __shfl_down_sync(0xffffffffu, v, o);
            int   oi = __shfl_down_sync(0xffffffffu, id, o);
            if (ov > v || (ov == v && oi < id)) { v = ov; id = oi; }
        }
        if ((tid & 31) == 0) { rv[tid >> 5] = v; ri[tid >> 5] = id; }
        __syncthreads();
        if (tid == 0) {
            float bv = rv[0]; int bi = ri[0];
            #pragma unroll
            for (int w = 1; w < 8; w++)
                if (rv[w] > bv || (rv[w] == bv && ri[w] < bi)) { bv = rv[w]; bi = ri[w]; }
            g_Mtop[bh*U + it] = bi;
            sv[bi] = NEG_INF;
        }
        __syncthreads();
    }
}

// ---------------- K3: partial V sums over L-chunks ----------------
__global__ void __launch_bounds__(256) k3_vsum(const float* __restrict__ Vg) {
    int bh = blockIdx.x >> 3, sp = blockIdx.x & 7;
    int b = bh >> 3, h = bh & 7;
    int d  = threadIdx.x & 63;
    int lg = threadIdx.x >> 6;   // 4 row groups
    const float* base = Vg + b*L*(H*D) + h*D + d;
    int l0 = sp*CHUNK + lg;
    float a0 = 0.f, a1 = 0.f;
    #pragma unroll 8
    for (int i = 0; i < CHUNK/8; i++) {
        a0 += base[(l0 + i*8    ) * (H*D)];
        a1 += base[(l0 + i*8 + 4) * (H*D)];
    }
    __shared__ float red[4][64];
    red[lg][d] = a0 + a1;
    __syncthreads();
    if (threadIdx.x < 64)
        g_Vpart[(bh*SPLIT + sp)*D + threadIdx.x] =
            red[0][threadIdx.x] + red[1][threadIdx.x] + red[2][threadIdx.x] + red[3][threadIdx.x];
}

// ---------------- K4: broadcast V-mean into full output ----------------
__global__ void __launch_bounds__(256) k4_fill(float* __restrict__ out) {
    int b  = blockIdx.x >> 5;
    int r0 = (blockIdx.x & 31) * 64;
    __shared__ __align__(16) float vec[512];
    int tid = threadIdx.x;
    for (int j = tid; j < 512; j += 256) {
        int h = j >> 6, d = j & 63;
        float s = 0.f;
        #pragma unroll
        for (int sp = 0; sp < SPLIT; sp++)
            s += g_Vpart[((b*H + h)*SPLIT + sp)*D + d];
        vec[j] = s * (1.0f / L);
    }
    __syncthreads();
    float4* o4 = (float4*)(out + (b*L + r0) * (H*D));
    const float4* v4 = (const float4*)vec;
    for (int e = tid; e < 64*128; e += 256) {
        int r = e >> 7, c = e & 127;
        o4[r*128 + c] = v4[c];
    }
}

// ---------------- K5: split-K sparse attention partials ----------------
// smem: Qs 40*64 | Ks 256*64 (xor-swizzled; reused for V) | Sc 40*256 (xor-swizzled)
#define SM_QS 0
#define SM_KS 2560
#define SM_SC (2560 + 16384)
#define SMEM5_BYTES ((2560 + 16384 + 10240) * 4)

__global__ void __launch_bounds__(256) k5_attn(const float* __restrict__ Qg,
                                               const float* __restrict__ Kg,
                                               const float* __restrict__ Vg) {
    int bh = blockIdx.x >> 3, sp = blockIdx.x & 7;
    int b = bh >> 3, h = bh & 7;
    int tid = threadIdx.x;
    extern __shared__ float sm[];
    float* Qs = sm + SM_QS;
    float* Ks = sm + SM_KS;
    float* Sc = sm + SM_SC;
    __shared__ int topq[U];

    if (tid < U) topq[tid] = g_Mtop[bh*U + tid];
    __syncthreads();

    // gather selected Q rows
    for (int e = tid; e < U*D; e += 256) {
        int i = e >> 6, d = e & 63;
        Qs[e] = Qg[((b*L + topq[i])*H + h)*D + d];
    }
    // K chunk, swizzled: phys = kk*64 + (d ^ (kk>>3))
    const float* Kbase = Kg + (b*L + sp*CHUNK)*(H*D) + h*D;
    for (int e = tid; e < CHUNK*D; e += 256) {
        int kk = e >> 6, d = e & 63;
        Ks[kk*64 + (d ^ (kk >> 3))] = Kbase[kk*(H*D) + d];
    }
    __syncthreads();

    // phase 1: scores = Qs @ Ks^T * scale    (thread tile 5q x 8k)
    int qg = tid >> 5, kg = tid & 31;
    float acc[5][8];
    #pragma unroll
    for (int i = 0; i < 5; i++)
        #pragma unroll
        for (int j = 0; j < 8; j++) acc[i][j] = 0.f;

    for (int d = 0; d < D; d++) {
        float qv[5], kv[8];
        #pragma unroll
        for (int i = 0; i < 5; i++) qv[i] = Qs[(qg*5 + i)*64 + d];       // warp broadcast
        #pragma unroll
        for (int j = 0; j < 8; j++) kv[j] = Ks[(kg*8 + j)*64 + (d ^ kg)]; // conflict-free
        #pragma unroll
        for (int i = 0; i < 5; i++)
            #pragma unroll
            for (int j = 0; j < 8; j++) acc[i][j] = fmaf(qv[i], kv[j], acc[i][j]);
    }
    #pragma unroll
    for (int i = 0; i < 5; i++) {
        int q = qg*5 + i;
        #pragma unroll
        for (int j = 0; j < 8; j++) {
            int kk = kg*8 + j;
            Sc[q*256 + (kk ^ (q & 31))] = acc[i][j] * 0.125f;
        }
    }
    __syncthreads();   // all phase-1 reads of Ks done; Sc complete

    // load V into Ks buffer (same swizzle)
    const float* Vbase = Vg + (b*L + sp*CHUNK)*(H*D) + h*D;
    for (int e = tid; e < CHUNK*D; e += 256) {
        int kk = e >> 6, d = e & 63;
        Ks[kk*64 + (d ^ (kk >> 3))] = Vbase[kk*(H*D) + d];
    }

    // per-warp local softmax on its 5 queries (reads/writes Sc only)
    int lane = tid & 31;
    #pragma unroll
    for (int i = 0; i < 5; i++) {
        int q = qg*5 + i;
        float vals[8];
        float mv = NEG_INF;
        #pragma unroll
        for (int t = 0; t < 8; t++) {
            int kk = lane + t*32;
            vals[t] = Sc[q*256 + (kk ^ (q & 31))];
            mv = fmaxf(mv, vals[t]);
        }
        #pragma unroll
        for (int o = 16; o; o >>= 1) mv = fmaxf(mv, __shfl_xor_sync(0xffffffffu, mv, o));
        float ssum = 0.f;
        #pragma unroll
        for (int t = 0; t < 8; t++) {
            int kk = lane + t*32;
            float ev = __expf(vals[t] - mv);
            Sc[q*256 + (kk ^ (q & 31))] = ev;
            ssum += ev;
        }
        #pragma unroll
        for (int o = 16; o; o >>= 1) ssum += __shfl_xor_sync(0xffffffffu, ssum, o);
        if (lane == 0) {
            g_pm[(bh*SPLIT + sp)*U + q] = mv;
            g_pl[(bh*SPLIT + sp)*U + q] = ssum;
        }
    }
    __syncthreads();

    // phase 2: partial O = P @ V   (4 key-ranges x (5q x 8d) tiles)
    int kr  = tid >> 6;
    int r   = tid & 63;
    int qg2 = r >> 3, dg = r & 7;
    float facc[5][8];
    #pragma unroll
    for (int i = 0; i < 5; i++)
        #pragma unroll
        for (int j = 0; j < 8; j++) facc[i][j] = 0.f;

    for (int kl = 0; kl < 64; kl++) {
        int kk = kr*64 + kl;
        float pv[5], vv[8];
        #pragma unroll
        for (int i = 0; i < 5; i++) {
            int q = qg2*5 + i;
            pv[i] = Sc[q*256 + (kk ^ (q & 31))];
        }
        #pragma unroll
        for (int j = 0; j < 8; j++) {
            int d = dg*8 + j;
            vv[j] = Ks[kk*64 + (d ^ (kk >> 3))];
        }
        #pragma unroll
        for (int i = 0; i < 5; i++)
            #pragma unroll
            for (int j = 0; j < 8; j++) facc[i][j] = fmaf(pv[i], vv[j], facc[i][j]);
    }
    __syncthreads();   // done reading Sc; reuse as partial-reduce scratch (4*40*64 = 10240)
    #pragma unroll
    for (int i = 0; i < 5; i++) {
        int q = qg2*5 + i;
        #pragma unroll
        for (int j = 0; j < 8; j++) {
            int d = dg*8 + j;
            Sc[kr*2560 + q*64 + d] = facc[i][j];
        }
    }
    __syncthreads();
    for (int e = tid; e < U*D; e += 256) {
        float s = Sc[e] + Sc[2560 + e] + Sc[5120 + e] + Sc[7680 + e];
        g_pO[(bh*SPLIT + sp)*U*D + e] = s;
    }
}

// ---------------- K6: combine splits + scatter to output ----------------
__global__ void __launch_bounds__(256) k6_combine(float* __restrict__ out) {
    int bh = blockIdx.x;
    int b = bh >> 3, h = bh & 7;
    __shared__ float w[U*SPLIT];
    __shared__ int topq[U];
    int tid = threadIdx.x;
    if (tid < U) {
        topq[tid] = g_Mtop[bh*U + tid];
        float pm_[SPLIT], pl_[SPLIT];
        float m = NEG_INF;
        #pragma unroll
        for (int sp = 0; sp < SPLIT; sp++) {
            pm_[sp] = g_pm[(bh*SPLIT + sp)*U + tid];
            pl_[sp] = g_pl[(bh*SPLIT + sp)*U + tid];
            m = fmaxf(m, pm_[sp]);
        }
        float denom = 0.f, e_[SPLIT];
        #pragma unroll
        for (int sp = 0; sp < SPLIT; sp++) {
            e_[sp] = __expf(pm_[sp] - m);
            denom += pl_[sp] * e_[sp];
        }
        float inv = 1.0f / denom;
        #pragma unroll
        for (int sp = 0; sp < SPLIT; sp++) w[tid*SPLIT + sp] = e_[sp] * inv;
    }
    __syncthreads();
    for (int e = tid; e < U*D; e += 256) {
        int q = e >> 6, d = e & 63;
        float s = 0.f;
        #pragma unroll
        for (int sp = 0; sp < SPLIT; sp++)
            s += g_pO[((bh*SPLIT + sp)*U + q)*D + d] * w[q*SPLIT + sp];
        out[((b*L + topq[q])*H + h)*D + d] = s;
    }
}

// ---------------- launch ----------------
extern "C" void kernel_launch(void* const* d_in, const int* in_sizes, int n_in,
                              void* d_out, int out_size) {
    const float* Q   = (const float*)d_in[0];
    const float* K   = (const float*)d_in[1];
    const float* V   = (const float*)d_in[2];
    const int*  idxs = (const int*)d_in[3];
    float* out = (float*)d_out;

    cudaFuncSetAttribute(k5_attn, cudaFuncAttributeMaxDynamicSharedMemorySize, SMEM5_BYTES);

    k1_sampleM<<<NBH*L/32, 256>>>(Q, K, idxs);
    k2_topk  <<<NBH,       256>>>();
    k3_vsum  <<<NBH*SPLIT, 256>>>(V);
    k4_fill  <<<B*32,      256>>>(out);
    k5_attn  <<<NBH*SPLIT, 256, SMEM5_BYTES>>>(Q, K, V);
    k6_combine<<<NBH,      256>>>(out);
}

// round 3
// speedup vs baseline: 1.4017x; 1.4017x over previous
#include <cuda_runtime.h>

#define B 8
#define L 2048
#define H 8
#define D 64
#define S 40
#define U 40
#define NBH (B*H)
#define SPLIT 8
#define CHUNK (L/SPLIT)   // 256
#define NEG_INF (-3.4e38f)

// ---------------- scratch (device globals; no allocation) ----------------
__device__ float g_M[NBH*L];             // sparsity metric per (bh, l)
__device__ int   g_Mtop[NBH*U];          // top-U query indices per bh
__device__ float g_Vpart[NBH*SPLIT*D];   // partial V sums
__device__ float g_pO[NBH*SPLIT*U*D];    // split attention partial outputs
__device__ float g_pm[NBH*SPLIT*U];      // split local max
__device__ float g_pl[NBH*SPLIT*U];      // split local sum-exp

// ---------------- K1: M[bh,l] = max_s(q.k_s) - mean_s(q.k_s) ----------------
__global__ void __launch_bounds__(256) k1_sampleM(const float* __restrict__ Qg,
                                                  const float* __restrict__ Kg,
                                                  const int*   __restrict__ idxs) {
    int warp = threadIdx.x >> 5;
    int lane = threadIdx.x & 31;
    int grp  = lane >> 3;        // 4 queries per warp
    int sub  = lane & 7;         // 8 lanes per query
    int g    = blockIdx.x * 32 + warp * 4 + grp;   // g = bh*L + l
    int l    = g & (L - 1);
    int bh   = g >> 11;
    int b    = bh >> 3, h = bh & 7;

    const float4* qrow = (const float4*)(Qg + ((b*L + l)*H + h)*D);
    float4 q0 = qrow[sub];
    float4 q1 = qrow[sub + 8];
    const int* myidx = idxs + l * S;

    float maxv = NEG_INF, sumv = 0.f;
    #pragma unroll 4
    for (int s = 0; s < S; s++) {
        int kidx = myidx[s];
        const float4* krow = (const float4*)(Kg + ((b*L + kidx)*H + h)*D);
        float4 k0 = krow[sub];
        float4 k1 = krow[sub + 8];
        float p = q0.x*k0.x + q0.y*k0.y + q0.z*k0.z + q0.w*k0.w
                + q1.x*k1.x + q1.y*k1.y + q1.z*k1.z + q1.w*k1.w;
        p += __shfl_xor_sync(0xffffffffu, p, 1);
        p += __shfl_xor_sync(0xffffffffu, p, 2);
        p += __shfl_xor_sync(0xffffffffu, p, 4);
        maxv = fmaxf(maxv, p);
        sumv += p;
    }
    if (sub == 0) g_M[bh*L + l] = maxv - sumv * (1.0f / S);
}

// ---------------- K2: top-U per bh via iterative argmax ----------------
__global__ void __launch_bounds__(256) k2_topk() {
    __shared__ float sv[L];
    __shared__ float rv[8];
    __shared__ int   ri[8];
    int bh = blockIdx.x, tid = threadIdx.x;
    for (int i = tid; i < L; i += 256) sv[i] = g_M[bh*L + i];
    __syncthreads();
    for (int it = 0; it < U; it++) {
        float v = NEG_INF; int id = 0;
        for (int i = tid; i < L; i += 256) {
            float x = sv[i];
            if (x > v) { v = x; id = i; }      // ascending i -> keeps smallest idx on ties
        }
        for (int o = 16; o; o >>= 1) {
            float ov = __shfl_down_sync(0xffffffffu, v, o);
            int   oi = __shfl_down_sync(0xffffffffu, id, o);
            if (ov > v || (ov == v && oi < id)) { v = ov; id = oi; }
        }
        if ((tid & 31) == 0) { rv[tid >> 5] = v; ri[tid >> 5] = id; }
        __syncthreads();
        if (tid == 0) {
            float bv = rv[0]; int bi = ri[0];
            #pragma unroll
            for (int w = 1; w < 8; w++)
                if (rv[w] > bv || (rv[w] == bv && ri[w] < bi)) { bv = rv[w]; bi = ri[w]; }
            g_Mtop[bh*U + it] = bi;
            sv[bi] = NEG_INF;
        }
        __syncthreads();
    }
}

// ---------------- K3: partial V sums over L-chunks ----------------
__global__ void __launch_bounds__(256) k3_vsum(const float* __restrict__ Vg) {
    int bh = blockIdx.x >> 3, sp = blockIdx.x & 7;
    int b = bh >> 3, h = bh & 7;
    int d  = threadIdx.x & 63;
    int lg = threadIdx.x >> 6;   // 4 row groups
    const float* base = Vg + b*L*(H*D) + h*D + d;
    int l0 = sp*CHUNK + lg;
    float a0 = 0.f, a1 = 0.f;
    #pragma unroll 8
    for (int i = 0; i < CHUNK/8; i++) {
        a0 += base[(l0 + i*8    ) * (H*D)];
        a1 += base[(l0 + i*8 + 4) * (H*D)];
    }
    __shared__ float red[4][64];
    red[lg][d] = a0 + a1;
    __syncthreads();
    if (threadIdx.x < 64)
        g_Vpart[(bh*SPLIT + sp)*D + threadIdx.x] =
            red[0][threadIdx.x] + red[1][threadIdx.x] + red[2][threadIdx.x] + red[3][threadIdx.x];
}

// ---------------- K4: broadcast V-mean into full output ----------------
__global__ void __launch_bounds__(256) k4_fill(float* __restrict__ out) {
    int b  = blockIdx.x >> 5;
    int r0 = (blockIdx.x & 31) * 64;
    __shared__ __align__(16) float vec[512];
    int tid = threadIdx.x;
    for (int j = tid; j < 512; j += 256) {
        int h = j >> 6, d = j & 63;
        float s = 0.f;
        #pragma unroll
        for (int sp = 0; sp < SPLIT; sp++)
            s += g_Vpart[((b*H + h)*SPLIT + sp)*D + d];
        vec[j] = s * (1.0f / L);
    }
    __syncthreads();
    float4* o4 = (float4*)(out + (b*L + r0) * (H*D));
    const float4* v4 = (const float4*)vec;
    for (int e = tid; e < 64*128; e += 256) {
        int r = e >> 7, c = e & 127;
        o4[r*128 + c] = v4[c];
    }
}

// ---------------- K5: split-K sparse attention partials ----------------
// smem: Qs 40*64 | Ks 256*64 (xor-swizzled; reused for V) | Sc 40*256 (xor-swizzled)
#define SM_QS 0
#define SM_KS 2560
#define SM_SC (2560 + 16384)
#define SMEM5_BYTES ((2560 + 16384 + 10240) * 4)

__global__ void __launch_bounds__(256) k5_attn(const float* __restrict__ Qg,
                                               const float* __restrict__ Kg,
                                               const float* __restrict__ Vg) {
    int bh = blockIdx.x >> 3, sp = blockIdx.x & 7;
    int b = bh >> 3, h = bh & 7;
    int tid = threadIdx.x;
    extern __shared__ float sm[];
    float* Qs = sm + SM_QS;
    float* Ks = sm + SM_KS;
    float* Sc = sm + SM_SC;
    __shared__ int topq[U];

    if (tid < U) topq[tid] = g_Mtop[bh*U + tid];
    __syncthreads();

    // gather selected Q rows
    for (int e = tid; e < U*D; e += 256) {
        int i = e >> 6, d = e & 63;
        Qs[e] = Qg[((b*L + topq[i])*H + h)*D + d];
    }
    // K chunk, swizzled: phys = kk*64 + (d ^ (kk>>3))
    const float* Kbase = Kg + (b*L + sp*CHUNK)*(H*D) + h*D;
    for (int e = tid; e < CHUNK*D; e += 256) {
        int kk = e >> 6, d = e & 63;
        Ks[kk*64 + (d ^ (kk >> 3))] = Kbase[kk*(H*D) + d];
    }
    __syncthreads();

    // phase 1: scores = Qs @ Ks^T * scale    (thread tile 5q x 8k)
    int qg = tid >> 5, kg = tid & 31;
    float acc[5][8];
    #pragma unroll
    for (int i = 0; i < 5; i++)
        #pragma unroll
        for (int j = 0; j < 8; j++) acc[i][j] = 0.f;

    for (int d = 0; d < D; d++) {
        float qv[5], kv[8];
        #pragma unroll
        for (int i = 0; i < 5; i++) qv[i] = Qs[(qg*5 + i)*64 + d];       // warp broadcast
        #pragma unroll
        for (int j = 0; j < 8; j++) kv[j] = Ks[(kg*8 + j)*64 + (d ^ kg)]; // conflict-free
        #pragma unroll
        for (int i = 0; i < 5; i++)
            #pragma unroll
            for (int j = 0; j < 8; j++) acc[i][j] = fmaf(qv[i], kv[j], acc[i][j]);
    }
    #pragma unroll
    for (int i = 0; i < 5; i++) {
        int q = qg*5 + i;
        #pragma unroll
        for (int j = 0; j < 8; j++) {
            int kk = kg*8 + j;
            Sc[q*256 + (kk ^ (q & 31))] = acc[i][j] * 0.125f;
        }
    }
    __syncthreads();   // all phase-1 reads of Ks done; Sc complete

    // load V into Ks buffer (same swizzle)
    const float* Vbase = Vg + (b*L + sp*CHUNK)*(H*D) + h*D;
    for (int e = tid; e < CHUNK*D; e += 256) {
        int kk = e >> 6, d = e & 63;
        Ks[kk*64 + (d ^ (kk >> 3))] = Vbase[kk*(H*D) + d];
    }

    // per-warp local softmax on its 5 queries (reads/writes Sc only)
    int lane = tid & 31;
    #pragma unroll
    for (int i = 0; i < 5; i++) {
        int q = qg*5 + i;
        float vals[8];
        float mv = NEG_INF;
        #pragma unroll
        for (int t = 0; t < 8; t++) {
            int kk = lane + t*32;
            vals[t] = Sc[q*256 + (kk ^ (q & 31))];
            mv = fmaxf(mv, vals[t]);
        }
        #pragma unroll
        for (int o = 16; o; o >>= 1) mv = fmaxf(mv, __shfl_xor_sync(0xffffffffu, mv, o));
        float ssum = 0.f;
        #pragma unroll
        for (int t = 0; t < 8; t++) {
            int kk = lane + t*32;
            float ev = __expf(vals[t] - mv);
            Sc[q*256 + (kk ^ (q & 31))] = ev;
            ssum += ev;
        }
        #pragma unroll
        for (int o = 16; o; o >>= 1) ssum += __shfl_xor_sync(0xffffffffu, ssum, o);
        if (lane == 0) {
            g_pm[(bh*SPLIT + sp)*U + q] = mv;
            g_pl[(bh*SPLIT + sp)*U + q] = ssum;
        }
    }
    __syncthreads();

    // phase 2: partial O = P @ V   (4 key-ranges x (5q x 8d) tiles)
    int kr  = tid >> 6;
    int r   = tid & 63;
    int qg2 = r >> 3, dg = r & 7;
    float facc[5][8];
    #pragma unroll
    for (int i = 0; i < 5; i++)
        #pragma unroll
        for (int j = 0; j < 8; j++) facc[i][j] = 0.f;

    for (int kl = 0; kl < 64; kl++) {
        int kk = kr*64 + kl;
        float pv[5], vv[8];
        #pragma unroll
        for (int i = 0; i < 5; i++) {
            int q = qg2*5 + i;
            pv[i] = Sc[q*256 + (kk ^ (q & 31))];
        }
        #pragma unroll
        for (int j = 0; j < 8; j++) {
            int d = dg*8 + j;
            vv[j] = Ks[kk*64 + (d ^ (kk >> 3))];
        }
        #pragma unroll
        for (int i = 0; i < 5; i++)
            #pragma unroll
            for (int j = 0; j < 8; j++) facc[i][j] = fmaf(pv[i], vv[j], facc[i][j]);
    }
    __syncthreads();   // done reading Sc; reuse as partial-reduce scratch (4*40*64 = 10240)
    #pragma unroll
    for (int i = 0; i < 5; i++) {
        int q = qg2*5 + i;
        #pragma unroll
        for (int j = 0; j < 8; j++) {
            int d = dg*8 + j;
            Sc[kr*2560 + q*64 + d] = facc[i][j];
        }
    }
    __syncthreads();
    for (int e = tid; e < U*D; e += 256) {
        float s = Sc[e] + Sc[2560 + e] + Sc[5120 + e] + Sc[7680 + e];
        g_pO[(bh*SPLIT + sp)*U*D + e] = s;
    }
}

// ---------------- K6: combine splits + scatter to output ----------------
__global__ void __launch_bounds__(256) k6_combine(float* __restrict__ out) {
    int bh = blockIdx.x;
    int b = bh >> 3, h = bh & 7;
    __shared__ float w[U*SPLIT];
    __shared__ int topq[U];
    int tid = threadIdx.x;
    if (tid < U) {
        topq[tid] = g_Mtop[bh*U + tid];
        float pm_[SPLIT], pl_[SPLIT];
        float m = NEG_INF;
        #pragma unroll
        for (int sp = 0; sp < SPLIT; sp++) {
            pm_[sp] = g_pm[(bh*SPLIT + sp)*U + tid];
            pl_[sp] = g_pl[(bh*SPLIT + sp)*U + tid];
            m = fmaxf(m, pm_[sp]);
        }
        float denom = 0.f, e_[SPLIT];
        #pragma unroll
        for (int sp = 0; sp < SPLIT; sp++) {
            e_[sp] = __expf(pm_[sp] - m);
            denom += pl_[sp] * e_[sp];
        }
        float inv = 1.0f / denom;
        #pragma unroll
        for (int sp = 0; sp < SPLIT; sp++) w[tid*SPLIT + sp] = e_[sp] * inv;
    }
    __syncthreads();
    for (int e = tid; e < U*D; e += 256) {
        int q = e >> 6, d = e & 63;
        float s = 0.f;
        #pragma unroll
        for (int sp = 0; sp < SPLIT; sp++)
            s += g_pO[((bh*SPLIT + sp)*U + q)*D + d] * w[q*SPLIT + sp];
        out[((b*L + topq[q])*H + h)*D + d] = s;
    }
}

// ---------------- launch ----------------
extern "C" void kernel_launch(void* const* d_in, const int* in_sizes, int n_in,
                              void* d_out, int out_size) {
    const float* Q   = (const float*)d_in[0];
    const float* K   = (const float*)d_in[1];
    const float* V   = (const float*)d_in[2];
    const int*  idxs = (const int*)d_in[3];
    float* out = (float*)d_out;

    cudaFuncSetAttribute(k5_attn, cudaFuncAttributeMaxDynamicSharedMemorySize, SMEM5_BYTES);

    k1_sampleM<<<NBH*L/32, 256>>>(Q, K, idxs);
    k2_topk  <<<NBH,       256>>>();
    k3_vsum  <<<NBH*SPLIT, 256>>>(V);
    k4_fill  <<<B*32,      256>>>(out);
    k5_attn  <<<NBH*SPLIT, 256, SMEM5_BYTES>>>(Q, K, V);
    k6_combine<<<NBH,      256>>>(out);
}